// round 17
// baseline (speedup 1.0000x reference)
#include <cuda_runtime.h>
#include <cuda_fp16.h>
#include <cstdint>
#include <cstring>

#define DD 128
#define NPAD 50048
#define GMAXC 64
#define CAP 128                // adjacency bucket capacity per node
#define SA 136                 // smem row stride in halves (conflict-free layout)
#define MROWS 128              // rows per GEMM CTA

// ---- scratch (device globals; no allocation allowed) ----
// double-buffered fp16 message/self sets (half2-packed u32, 64/row)
__device__ uint32_t g_hXd[2][(size_t)NPAD * 64];
__device__ uint32_t g_hXc[2][(size_t)NPAD * 64];
__device__ uint32_t g_hSelf[2][(size_t)NPAD * 64];
__device__ float g_cnt[GMAXC];
__device__ float g_bias[9][DD];     // [layer*3+family][col]

// bucketed adjacency
__device__ int g_deg[NPAD];
__device__ int g_adj[(size_t)NPAD * CAP];   // packed: src | (type<<31)

// fp16 weight images, TRANSPOSED [n][k], packed as u32 (k, k+1) pairs
__device__ uint32_t g_Wh[9][8192];

// ============================================================
// Weight prep: W -> fp16, transposed [n][k]; biases to table
// ============================================================
__global__ void prep_w_kernel(const float* __restrict__ Wd,
                              const float* __restrict__ Wc,
                              const float* __restrict__ Ws,
                              const float* __restrict__ bd,
                              const float* __restrict__ bc,
                              const float* __restrict__ bs)
{
    int img = blockIdx.x;
    int layer = img / 3, f = img % 3;
    const float* W = ((f == 0) ? Wd : (f == 1) ? Wc : Ws) + (size_t)layer * DD * DD;
    const float* b = (f == 0) ? bd : ((f == 1) ? bc : bs);
    int n = threadIdx.x;

    g_bias[img][n] = b[layer * DD + n];

    uint32_t* Hi = g_Wh[img];
    for (int k = 0; k < DD; k += 2) {
        float x0 = W[(size_t)k * DD + n];
        float x1 = W[(size_t)(k + 1) * DD + n];
        __half2 h = __floats2half2_rn(x0, x1);
        uint32_t hp;
        memcpy(&hp, &h, 4);
        Hi[n * 64 + (k >> 1)] = hp;
    }
}

// ============================================================
// init: zero deg, zero pool output, per-graph counts (binary search
// on sorted batch_ids -> no atomics)
// ============================================================
__global__ void init_kernel(const int* __restrict__ bid, float* __restrict__ out,
                            int out_size, int N, int G)
{
    int i = blockIdx.x * blockDim.x + threadIdx.x;
    if (i < out_size) out[i] = 0.f;
    if (i < N) g_deg[i] = 0;
    if (i < G) {
        int lo = 0, hi = N;
        while (lo < hi) { int m = (lo + hi) >> 1; if (bid[m] < i) lo = m + 1; else hi = m; }
        int lb = lo;
        lo = 0; hi = N;
        while (lo < hi) { int m = (lo + hi) >> 1; if (bid[m] <= i) lo = m + 1; else hi = m; }
        g_cnt[i] = (float)(lo - lb);
    }
}

// ============================================================
// Bucket adjacency build: one pass over edges
// ============================================================
__global__ void bucket_kernel(const int* __restrict__ ei,
                              const int* __restrict__ et, int E)
{
    int e = blockIdx.x * blockDim.x + threadIdx.x;
    if (e >= E) return;
    int src = ei[e];
    int dst = ei[E + e];
    int t   = et[e];
    int pos = atomicAdd(&g_deg[dst], 1);
    if (pos < CAP)
        g_adj[(size_t)dst * CAP + pos] = src | (t << 31);
}

// ============================================================
// Fused GEMM (+optional agg prologue)
// ============================================================
#define MMA_F16(c, a0, a1, a2, a3, b0, b1)                                     \
    asm volatile("mma.sync.aligned.m16n8k16.row.col.f32.f16.f16.f32 "          \
                 "{%0,%1,%2,%3}, {%4,%5,%6,%7}, {%8,%9}, {%0,%1,%2,%3};"       \
                 : "+f"(c[0]), "+f"(c[1]), "+f"(c[2]), "+f"(c[3])              \
                 : "r"(a0), "r"(a1), "r"(a2), "r"(a3), "r"(b0), "r"(b1))

#define LDSM_X4(r0, r1, r2, r3, addr)                                          \
    asm volatile("ldmatrix.sync.aligned.m8n8.x4.shared.b16 {%0,%1,%2,%3}, [%4];" \
                 : "=r"(r0), "=r"(r1), "=r"(r2), "=r"(r3) : "r"(addr))

#define LDSM_X2(r0, r1, addr)                                                  \
    asm volatile("ldmatrix.sync.aligned.m8n8.x2.shared.b16 {%0,%1}, [%2];"     \
                 : "=r"(r0), "=r"(r1) : "r"(addr))

#define SM_BIAS 0
#define SM_AH   1536
#define SM_B0   (SM_AH + MROWS * SA * 2)
#define SM_B1   (SM_B0 + 128 * SA * 2)
#define SM_GTOT (SM_B1 + 128 * SA * 2)   // 105984 -> 2 CTAs/SM

__device__ __forceinline__ uint32_t smem_u32(const void* p) {
    uint32_t a;
    asm("{ .reg .u64 t; cvta.to.shared.u64 t, %1; cvt.u32.u64 %0, t; }"
        : "=r"(a) : "l"(p));
    return a;
}

__device__ __forceinline__ void copy_b(__half* B, const uint32_t* src, int tid) {
    const uint4* s = (const uint4*)src;
#pragma unroll
    for (int j = 0; j < 8; j++) {
        int i = tid + j * 256;
        int rr = i >> 4, c16 = i & 15;
        *(uint4*)&B[rr * SA + c16 * 8] = s[i];
    }
}

__global__ __launch_bounds__(256, 2) void gemm_mma_kernel(
    const float* __restrict__ Xext, int agg_rd, int wr, int layer, int N)
{
    extern __shared__ char smem[];
    float* bias_s = (float*)(smem + SM_BIAS);
    __half* Ah = (__half*)(smem + SM_AH);
    __half* B0 = (__half*)(smem + SM_B0);
    __half* B1 = (__half*)(smem + SM_B1);

    const int tid = threadIdx.x, wid = tid >> 5, lane = tid & 31;
    const int row0 = blockIdx.x * MROWS;
    const int img0 = layer * 3;

    if (tid < 128) {
        bias_s[tid]       = g_bias[img0 + 0][tid];
        bias_s[128 + tid] = g_bias[img0 + 1][tid];
        bias_s[256 + tid] = g_bias[img0 + 2][tid];
    }

    // ---- A prologue ----
    if (agg_rd < 0) {
        int r  = tid >> 1;
        int gr = row0 + r;
        bool ok = gr < N;
        int c0 = (tid & 1) * 64;
        const float4* xp = (const float4*)(Xext + (size_t)gr * DD + c0);
        uint32_t* ah = (uint32_t*)&Ah[r * SA + c0];
#pragma unroll
        for (int c4 = 0; c4 < 16; c4++) {
            float4 v = ok ? __ldg(xp + c4) : make_float4(0.f, 0.f, 0.f, 0.f);
            __half2 h01 = __floats2half2_rn(v.x, v.y);
            __half2 h23 = __floats2half2_rn(v.z, v.w);
            uint32_t hp0, hp1;
            memcpy(&hp0, &h01, 4); memcpy(&hp1, &h23, 4);
            ah[c4 * 2] = hp0; ah[c4 * 2 + 1] = hp1;
        }
    } else {
        // fused aggregation: warp w aggregates rows [w*16, w*16+16)
        const uint32_t* mXd = g_hXd[agg_rd];
        const uint32_t* mXc = g_hXc[agg_rd];
        const uint32_t* mS  = g_hSelf[agg_rd];
        for (int rr = 0; rr < 16; rr++) {
            int row = wid * 16 + rr;
            int node = row0 + row;
            float4 acc = make_float4(0.f, 0.f, 0.f, 0.f);
            if (node < N) {
                uint2 sv = *(const uint2*)(mS + (size_t)node * 64 + lane * 2);
                __half2 s0, s1;
                memcpy(&s0, &sv.x, 4); memcpy(&s1, &sv.y, 4);
                float2 f0 = __half22float2(s0);
                float2 f1 = __half22float2(s1);
                acc = make_float4(f0.x, f0.y, f1.x, f1.y);

                int deg = g_deg[node]; if (deg > CAP) deg = CAP;
                int beg = node * CAP;
                int end = beg + deg;
                for (int base = beg; base < end; base += 32) {
                    int cnt = end - base; if (cnt > 32) cnt = 32;
                    int idx = (base + lane < end) ? g_adj[base + lane] : 0;
                    int q = 0;
                    for (; q + 4 <= cnt; q += 4) {
                        uint2 v[4];
#pragma unroll
                        for (int u = 0; u < 4; u++) {
                            int p = __shfl_sync(0xffffffffu, idx, q + u);
                            const uint32_t* bp = (p < 0) ? mXc : mXd;
                            v[u] = *(const uint2*)(bp + (size_t)(p & 0x7fffffff) * 64 + lane * 2);
                        }
#pragma unroll
                        for (int u = 0; u < 4; u++) {
                            __half2 h0, h1;
                            memcpy(&h0, &v[u].x, 4); memcpy(&h1, &v[u].y, 4);
                            float2 g0 = __half22float2(h0);
                            float2 g1 = __half22float2(h1);
                            acc.x += g0.x; acc.y += g0.y;
                            acc.z += g1.x; acc.w += g1.y;
                        }
                    }
                    for (; q < cnt; q++) {
                        int p = __shfl_sync(0xffffffffu, idx, q);
                        const uint32_t* bp = (p < 0) ? mXc : mXd;
                        uint2 v = *(const uint2*)(bp + (size_t)(p & 0x7fffffff) * 64 + lane * 2);
                        __half2 h0, h1;
                        memcpy(&h0, &v.x, 4); memcpy(&h1, &v.y, 4);
                        float2 g0 = __half22float2(h0);
                        float2 g1 = __half22float2(h1);
                        acc.x += g0.x; acc.y += g0.y;
                        acc.z += g1.x; acc.w += g1.y;
                    }
                }
                acc.x = fmaxf(acc.x, 0.f); acc.y = fmaxf(acc.y, 0.f);
                acc.z = fmaxf(acc.z, 0.f); acc.w = fmaxf(acc.w, 0.f);
            }
            __half2 h0 = __floats2half2_rn(acc.x, acc.y);
            __half2 h1 = __floats2half2_rn(acc.z, acc.w);
            uint2 u;
            memcpy(&u.x, &h0, 4); memcpy(&u.y, &h1, 4);
            *(uint2*)((uint32_t*)&Ah[row * SA] + lane * 2) = u;
        }
    }

    // B family 0 into buffer 0
    copy_b(B0, g_Wh[img0], tid);
    __syncthreads();

    // warp tiling: 4 m-groups (32 rows each = 2 m-tiles) x 2 n-groups (8 nt)
    const int mrow0 = (wid >> 1) * 32;
    const int nt0   = (wid & 1) * 8;
    const int r     = lane >> 2;
    const int cc    = (lane & 3) * 2;

    const int lr     = lane & 7;
    const int a_rowp = ((lane >> 3) & 1) * 8;
    const int a_kp   = (lane >> 4) * 16;
    const int b_kp   = ((lane >> 3) & 1) * 16;

    uint32_t aoff = (uint32_t)((lr + a_rowp) * SA * 2 + a_kp);
    uint32_t boff = (uint32_t)(lr * SA * 2 + b_kp);

    uint32_t ah0 = smem_u32(Ah) + (uint32_t)(mrow0 * SA * 2) + aoff;
    uint32_t ah1 = ah0 + (uint32_t)(16 * SA * 2);
    uint32_t bbase0 = smem_u32(B0) + (uint32_t)(nt0 * 8 * SA * 2) + boff;
    uint32_t bbase1 = smem_u32(B1) + (uint32_t)(nt0 * 8 * SA * 2) + boff;

    for (int f = 0; f < 3; f++) {
        uint32_t bcur = (f & 1) ? bbase1 : bbase0;
        __half* Bnxt = (f & 1) ? B0 : B1;

        uint4 stage[8];
        if (f < 2) {
            const uint4* s = (const uint4*)g_Wh[img0 + f + 1];
#pragma unroll
            for (int j = 0; j < 8; j++) stage[j] = __ldg(s + tid + j * 256);
        }

        float acc[2][8][4];
#pragma unroll
        for (int m = 0; m < 2; m++)
#pragma unroll
            for (int nt = 0; nt < 8; nt++)
#pragma unroll
                for (int q = 0; q < 4; q++) acc[m][nt][q] = 0.f;

#pragma unroll
        for (int ks = 0; ks < 8; ks++) {
            const uint32_t ko = (uint32_t)(ks * 32);
            uint32_t A0[4], A1[4];
            LDSM_X4(A0[0], A0[1], A0[2], A0[3], ah0 + ko);
            LDSM_X4(A1[0], A1[1], A1[2], A1[3], ah1 + ko);
            uint32_t bb[8][2];
#pragma unroll
            for (int nt = 0; nt < 8; nt++)
                LDSM_X2(bb[nt][0], bb[nt][1],
                        bcur + (uint32_t)(nt * 8 * SA * 2) + ko);
#pragma unroll
            for (int nt = 0; nt < 8; nt++) {
                MMA_F16(acc[0][nt], A0[0], A0[1], A0[2], A0[3], bb[nt][0], bb[nt][1]);
                MMA_F16(acc[1][nt], A1[0], A1[1], A1[2], A1[3], bb[nt][0], bb[nt][1]);
            }
        }

        if (f < 2) {
#pragma unroll
            for (int j = 0; j < 8; j++) {
                int i = tid + j * 256;
                int rr = i >> 4, c16 = i & 15;
                *(uint4*)&Bnxt[rr * SA + c16 * 8] = stage[j];
            }
        }

        // epilogue: +bias, fp16 half2 store
        const float* bv = bias_s + f * 128;
        uint32_t* hout = (f == 0) ? g_hXd[wr] : ((f == 1) ? g_hXc[wr] : g_hSelf[wr]);
#pragma unroll
        for (int m = 0; m < 2; m++) {
            int gr0 = row0 + mrow0 + m * 16 + r;
            int gr1 = gr0 + 8;
#pragma unroll
            for (int nt = 0; nt < 8; nt++) {
                int col = (nt0 + nt) * 8 + cc;
                float bx = bv[col], by = bv[col + 1];
                if (gr0 < N) {
                    __half2 h = __floats2half2_rn(acc[m][nt][0] + bx,
                                                  acc[m][nt][1] + by);
                    uint32_t u; memcpy(&u, &h, 4);
                    hout[(size_t)gr0 * 64 + (col >> 1)] = u;
                }
                if (gr1 < N) {
                    __half2 h = __floats2half2_rn(acc[m][nt][2] + bx,
                                                  acc[m][nt][3] + by);
                    uint32_t u; memcpy(&u, &h, 4);
                    hout[(size_t)gr1 * 64 + (col >> 1)] = u;
                }
            }
        }
        __syncthreads();
    }
}

// ============================================================
// Final aggregation + pool: one warp per node, red.add into out
// ============================================================
__global__ __launch_bounds__(256) void agg_pool_kernel(
    int N, int rd, const int* __restrict__ batch_ids, float* __restrict__ pout)
{
    int node = blockIdx.x * 8 + (threadIdx.x >> 5);
    int lane = threadIdx.x & 31;
    if (node >= N) return;

    const uint32_t* mXd = g_hXd[rd];
    const uint32_t* mXc = g_hXc[rd];
    const uint32_t* mS  = g_hSelf[rd];

    int deg = g_deg[node]; if (deg > CAP) deg = CAP;
    int beg = node * CAP;
    int end = beg + deg;

    float4 acc;
    {
        uint2 sv = *(const uint2*)(mS + (size_t)node * 64 + lane * 2);
        __half2 s0, s1;
        memcpy(&s0, &sv.x, 4); memcpy(&s1, &sv.y, 4);
        float2 f0 = __half22float2(s0);
        float2 f1 = __half22float2(s1);
        acc = make_float4(f0.x, f0.y, f1.x, f1.y);
    }

    for (int base = beg; base < end; base += 32) {
        int cnt = end - base; if (cnt > 32) cnt = 32;
        int idx = (base + lane < end) ? g_adj[base + lane] : 0;
        int q = 0;
        for (; q + 4 <= cnt; q += 4) {
            uint2 v[4];
#pragma unroll
            for (int u = 0; u < 4; u++) {
                int p = __shfl_sync(0xffffffffu, idx, q + u);
                const uint32_t* bp = (p < 0) ? mXc : mXd;
                v[u] = *(const uint2*)(bp + (size_t)(p & 0x7fffffff) * 64 + lane * 2);
            }
#pragma unroll
            for (int u = 0; u < 4; u++) {
                __half2 h0, h1;
                memcpy(&h0, &v[u].x, 4); memcpy(&h1, &v[u].y, 4);
                float2 f0 = __half22float2(h0);
                float2 f1 = __half22float2(h1);
                acc.x += f0.x; acc.y += f0.y;
                acc.z += f1.x; acc.w += f1.y;
            }
        }
        for (; q < cnt; q++) {
            int p = __shfl_sync(0xffffffffu, idx, q);
            const uint32_t* bp = (p < 0) ? mXc : mXd;
            uint2 v = *(const uint2*)(bp + (size_t)(p & 0x7fffffff) * 64 + lane * 2);
            __half2 h0, h1;
            memcpy(&h0, &v.x, 4); memcpy(&h1, &v.y, 4);
            float2 f0 = __half22float2(h0);
            float2 f1 = __half22float2(h1);
            acc.x += f0.x; acc.y += f0.y;
            acc.z += f1.x; acc.w += f1.y;
        }
    }

    acc.x = fmaxf(acc.x, 0.f); acc.y = fmaxf(acc.y, 0.f);
    acc.z = fmaxf(acc.z, 0.f); acc.w = fmaxf(acc.w, 0.f);

    int b = batch_ids[node];
    float* dp = pout + (size_t)b * DD + lane * 4;
    asm volatile("red.global.add.v4.f32 [%0], {%1,%2,%3,%4};"
                 :: "l"(dp), "f"(acc.x), "f"(acc.y), "f"(acc.z), "f"(acc.w)
                 : "memory");
}

__global__ void pool_div_kernel(float* __restrict__ out, int out_size)
{
    int i = blockIdx.x * blockDim.x + threadIdx.x;
    if (i >= out_size) return;
    out[i] = out[i] / fmaxf(g_cnt[i >> 7], 1.0f);
}

// ============================================================
// launch  (gemm layer 0 placed 4th so ncu -s captures it)
// ============================================================
extern "C" void kernel_launch(void* const* d_in, const int* in_sizes, int n_in,
                              void* d_out, int out_size)
{
    const float* X   = (const float*)d_in[0];
    const float* Wd  = (const float*)d_in[1];
    const float* bd  = (const float*)d_in[2];
    const float* Wc  = (const float*)d_in[3];
    const float* bc  = (const float*)d_in[4];
    const float* Ws  = (const float*)d_in[5];
    const float* bs  = (const float*)d_in[6];
    const int*   ei  = (const int*)d_in[7];
    const int*   et  = (const int*)d_in[8];
    const int*   bid = (const int*)d_in[9];
    float* out = (float*)d_out;

    const int N = in_sizes[0] / DD;
    const int E = in_sizes[8];
    const int G = out_size / DD;

    static bool attr_done = false;
    if (!attr_done) {
        cudaFuncSetAttribute(gemm_mma_kernel,
                             cudaFuncAttributeMaxDynamicSharedMemorySize, SM_GTOT);
        attr_done = true;
    }

    int gtiles = (N + MROWS - 1) / MROWS;
    int eblk  = (E + 255) / 256;
    int nwarp = (N + 7) / 8;
    int nb    = (N + 255) / 256;

    prep_w_kernel<<<9, 128>>>(Wd, Wc, Ws, bd, bc, bs);           // 1
    init_kernel<<<nb, 256>>>(bid, out, out_size, N, G);          // 2
    bucket_kernel<<<eblk, 256>>>(ei, et, E);                     // 3
    gemm_mma_kernel<<<gtiles, 256, SM_GTOT>>>(X, -1, 0, 0, N);   // 4 <- profiled

    // fused layers 1 and 2 (agg prologue + gemm)
    gemm_mma_kernel<<<gtiles, 256, SM_GTOT>>>(X, 0, 1, 1, N);    // 5
    gemm_mma_kernel<<<gtiles, 256, SM_GTOT>>>(X, 1, 0, 2, N);    // 6

    // final aggregation + mean pool
    agg_pool_kernel<<<nwarp, 256>>>(N, 0, bid, out);             // 7
    pool_div_kernel<<<(out_size + 255) / 256, 256>>>(out, out_size); // 8
}